// round 7
// baseline (speedup 1.0000x reference)
#include <cuda_runtime.h>
#include <cuda_bf16.h>
#include <cstdint>

// Problem constants
#define V_  20000
#define M_  32
#define E_  128
#define H_  4
#define N_  8192
#define L_  64
#define C_  128
#define WPB 2          // words per block in word_embed kernel

// conv doc tile geometry (unswizzled, bank-conflict-free stride)
#define DSTRIDE 132            // floats per row (132 mod 32 = 4 -> conflict-free)
#define DOCROWS 68             // 64 + 4 pad rows (pads only feed discarded t)
#define DOCN   (DOCROWS * DSTRIDE)

// ---------------- device scratch (no allocations allowed) ----------------
__device__ float g_word_embeds[V_ * E_];          // [V,E]
__device__ float g_wqT[E_ * E_];                  // [e][i] = Wq[i][e]
__device__ float g_wvT[E_ * E_];                  // [e][i] = Wv[i][e]
__device__ float g_woT[E_ * E_];                  // [e][i] = out_w[i][e]
__device__ float g_fcT[3 * C_ * E_];              // [i][c] = fc_w[c][i]
// fragment-packed tf32 conv weights: per kstep s: 8 ntile-pairs x 32 lanes x uint4
__device__ uint4 g_wmma[49152];
#define WOFF3 0
#define WOFF4 12288
#define WOFF5 28672

// ---------------- tf32 helpers ----------------
__device__ __forceinline__ uint32_t f2tf32(float x) {
    uint32_t u;
    asm("cvt.rna.tf32.f32 %0, %1;" : "=r"(u) : "f"(x));
    return u;
}

__device__ __forceinline__ void mma_tf32(float* d,
                                         uint32_t a0, uint32_t a1, uint32_t a2, uint32_t a3,
                                         uint32_t b0, uint32_t b1) {
    asm volatile(
        "mma.sync.aligned.m16n8k8.row.col.f32.tf32.tf32.f32 "
        "{%0,%1,%2,%3}, {%4,%5,%6,%7}, {%8,%9}, {%0,%1,%2,%3};"
        : "+f"(d[0]), "+f"(d[1]), "+f"(d[2]), "+f"(d[3])
        : "r"(a0), "r"(a1), "r"(a2), "r"(a3), "r"(b0), "r"(b1));
}

// ---------------- prep kernels (two launches: conv lands at ncu index 3) ----
#define PSEG0 (E_ * E_)
#define PSEG3 (3 * C_ * E_)
#define PREPA_TOTAL (3 * PSEG0 + PSEG3)
#define PW3   (3 * 16 * 1024)
#define PW4   (4 * 16 * 1024)
#define PW5   (5 * 16 * 1024)
#define PREPB_TOTAL (PW3 + PW4 + PW5)

__global__ void prep_a_kernel(const float* __restrict__ in_w,
                              const float* __restrict__ out_w,
                              const float* __restrict__ fc_w) {
    int idx = blockIdx.x * blockDim.x + threadIdx.x;
    if (idx >= PREPA_TOTAL) return;
    if (idx < PSEG0) {                                    // wqT
        int e = idx >> 7, i = idx & 127;
        g_wqT[idx] = in_w[i * E_ + e];
        return;
    }
    idx -= PSEG0;
    if (idx < PSEG0) {                                    // wvT (Wv rows 256..383)
        int e = idx >> 7, i = idx & 127;
        g_wvT[idx] = in_w[2 * E_ * E_ + i * E_ + e];
        return;
    }
    idx -= PSEG0;
    if (idx < PSEG0) {                                    // woT
        int e = idx >> 7, i = idx & 127;
        g_woT[idx] = out_w[i * E_ + e];
        return;
    }
    idx -= PSEG0;
    {                                                     // fcT
        int i = idx >> 7, c = idx & 127;
        g_fcT[idx] = fc_w[c * (3 * C_) + i];
    }
}

__device__ __forceinline__ void prep_wmma_one(const float* __restrict__ w, int K,
                                              int dst_off_u4, int idx) {
    int s    = idx >> 10;
    int rem  = idx & 1023;
    int p    = rem >> 7;
    int lane = (rem >> 2) & 31;
    int q    = rem & 3;
    int j  = s >> 4, ec = s & 15;
    int nt = 2 * p + (q >> 1);
    int kk = (lane & 3) + 4 * (q & 1);
    int c  = nt * 8 + (lane >> 2);
    int e  = ec * 8 + kk;
    float v = w[(c * E_ + e) * K + j];
    reinterpret_cast<uint32_t*>(g_wmma)[dst_off_u4 * 4 + idx] = f2tf32(v);
}

__global__ void prep_b_kernel(const float* __restrict__ w3,
                              const float* __restrict__ w4,
                              const float* __restrict__ w5) {
    int idx = blockIdx.x * blockDim.x + threadIdx.x;
    if (idx >= PREPB_TOTAL) return;
    if (idx < PW3) { prep_wmma_one(w3, 3, WOFF3, idx); return; }
    idx -= PW3;
    if (idx < PW4) { prep_wmma_one(w4, 4, WOFF4, idx); return; }
    idx -= PW4;
    prep_wmma_one(w5, 5, WOFF5, idx);
}

// ---------------- word embedding kernel: 2 words per block ----------------
struct WSmem {
    float ctx[WPB][M_][E_ + 1];
    float q[WPB][E_];
    float qh[WPB][E_];
    float g[WPB][H_][E_];
    float ch[WPB][H_][E_];
    float o[WPB][E_];
    float attn[WPB][H_][M_];
    float cb[WPB][H_];
    int   idx[WPB][M_];
    int   len[WPB];
};

__global__ __launch_bounds__(128) void word_embed_kernel(
    const int* __restrict__ word2news, const int* __restrict__ word2news_len,
    const float* __restrict__ table,
    const float* __restrict__ in_w, const float* __restrict__ in_b,
    const float* __restrict__ out_b,
    const float* __restrict__ wqT, const float* __restrict__ wvT,
    const float* __restrict__ woT)
{
    extern __shared__ char smem_raw[];
    WSmem& s = *reinterpret_cast<WSmem*>(smem_raw);

    const int v0 = blockIdx.x * WPB;
    const int tid = threadIdx.x;

    if (tid < WPB * M_) {
        int w = tid >> 5, m = tid & 31;
        s.idx[w][m] = word2news[(v0 + w) * M_ + m];
    }
    if (tid < WPB) s.len[tid] = word2news_len[v0 + tid];
    __syncthreads();

    #pragma unroll
    for (int w = 0; w < WPB; ++w)
        #pragma unroll 4
        for (int m = 0; m < M_; ++m)
            s.ctx[w][m][tid] = table[s.idx[w][m] * E_ + tid];
    __syncthreads();

    // masked mean query
    #pragma unroll
    for (int w = 0; w < WPB; ++w) {
        int len = s.len[w];
        float inv = 1.0f / (float)(len > 0 ? len : 1);
        float a = 0.0f;
        for (int m = 0; m < len; ++m) a += s.ctx[w][m][tid];
        s.q[w][tid] = a * inv;
    }
    __syncthreads();

    // qh = q @ Wq^T + bq
    {
        float acc[WPB];
        #pragma unroll
        for (int w = 0; w < WPB; ++w) acc[w] = 0.0f;
        #pragma unroll 4
        for (int e = 0; e < E_; ++e) {
            float wq = wqT[e * E_ + tid];
            #pragma unroll
            for (int w = 0; w < WPB; ++w) acc[w] += s.q[w][e] * wq;
        }
        float bq = in_b[tid];
        #pragma unroll
        for (int w = 0; w < WPB; ++w) s.qh[w][tid] = acc[w] + bq;
    }
    __syncthreads();

    // g_h[e] = sum_d qh[h*32+d] * Wk[h*32+d][e]
    #pragma unroll
    for (int h = 0; h < H_; ++h) {
        float acc[WPB];
        #pragma unroll
        for (int w = 0; w < WPB; ++w) acc[w] = 0.0f;
        #pragma unroll 4
        for (int d = 0; d < 32; ++d) {
            float wk = in_w[(E_ + h * 32 + d) * E_ + tid];
            #pragma unroll
            for (int w = 0; w < WPB; ++w) acc[w] += s.qh[w][h * 32 + d] * wk;
        }
        #pragma unroll
        for (int w = 0; w < WPB; ++w) s.g[w][h][tid] = acc[w];
    }
    if (tid < WPB * H_) {
        int w = tid >> 2, h = tid & 3;
        float c = 0.0f;
        for (int d = 0; d < 32; ++d) c += s.qh[w][h * 32 + d] * in_b[E_ + h * 32 + d];
        s.cb[w][h] = c;
    }
    __syncthreads();

    // scores + per-head warp softmax
    {
        const int h = tid >> 5, m = tid & 31;
        #pragma unroll
        for (int w = 0; w < WPB; ++w) {
            float sc = s.cb[w][h];
            #pragma unroll 8
            for (int e = 0; e < E_; ++e) sc += s.ctx[w][m][e] * s.g[w][h][e];
            sc *= 0.17677669529663688f;               // 1/sqrt(32)
            if (m >= s.len[w]) sc = -1e30f;
            float wm = sc;
            #pragma unroll
            for (int o = 16; o; o >>= 1) wm = fmaxf(wm, __shfl_xor_sync(0xFFFFFFFFu, wm, o));
            float p = __expf(sc - wm);
            float ps = p;
            #pragma unroll
            for (int o = 16; o; o >>= 1) ps += __shfl_xor_sync(0xFFFFFFFFu, ps, o);
            s.attn[w][h][m] = p / ps;
        }
    }
    __syncthreads();

    // ch_h[e] = sum_m attn[h,m]*ctx[m][e]
    #pragma unroll
    for (int w = 0; w < WPB; ++w)
        #pragma unroll
        for (int h = 0; h < H_; ++h) {
            float c = 0.0f;
            #pragma unroll 8
            for (int m = 0; m < M_; ++m) c += s.attn[w][h][m] * s.ctx[w][m][tid];
            s.ch[w][h][tid] = c;
        }
    __syncthreads();

    // o[i] = ch_{h(i)} . Wv[i] + bv[i]
    {
        const int h = tid >> 5;
        float acc[WPB];
        #pragma unroll
        for (int w = 0; w < WPB; ++w) acc[w] = 0.0f;
        #pragma unroll 4
        for (int e = 0; e < E_; ++e) {
            float wv = wvT[e * E_ + tid];
            #pragma unroll
            for (int w = 0; w < WPB; ++w) acc[w] += s.ch[w][h][e] * wv;
        }
        float bv = in_b[2 * E_ + tid];
        #pragma unroll
        for (int w = 0; w < WPB; ++w) s.o[w][tid] = acc[w] + bv;
    }
    __syncthreads();

    // out proj
    {
        float acc[WPB];
        #pragma unroll
        for (int w = 0; w < WPB; ++w) acc[w] = 0.0f;
        #pragma unroll 4
        for (int e = 0; e < E_; ++e) {
            float wo = woT[e * E_ + tid];
            #pragma unroll
            for (int w = 0; w < WPB; ++w) acc[w] += s.o[w][e] * wo;
        }
        float ob = out_b[tid];
        #pragma unroll
        for (int w = 0; w < WPB; ++w)
            g_word_embeds[(v0 + w) * E_ + tid] = (s.len[w] > 0) ? (acc[w] + ob) : 0.0f;
    }
}

// ---------------- conv (tf32 mma) + maxpool + FC: 2 news per block ----------
// 128 threads = 4 warps; warp = (news = w>>1, chalf = w&1).
// Each warp: ALL 64 t-rows (4 mtiles of 16) x 8 ntiles (its channel half).
// Phases write disjoint feats ranges -> no per-phase barrier; one barrier before FC.
template <int K>
__device__ __forceinline__ void conv_mma_phase(
    const uint4* __restrict__ Bg, const float* __restrict__ bias,
    const uint32_t* __restrict__ dbase,
    float* feats, int kidx, int lane, int chalf)
{
    constexpr int S = K * 16;
    constexpr int T = L_ - K + 1;

    float d[4][8][4];
    #pragma unroll
    for (int mt = 0; mt < 4; ++mt)
        #pragma unroll
        for (int nt = 0; nt < 8; ++nt)
            #pragma unroll
            for (int k = 0; k < 4; ++k) d[mt][nt][k] = 0.0f;

    for (int s = 0; s < S; ++s) {
        const int j = s >> 4, ec = s & 15;
        const uint32_t* dp = dbase + (j + (lane >> 2)) * DSTRIDE + ec * 8 + (lane & 3);
        uint32_t a[4][4];
        #pragma unroll
        for (int mt = 0; mt < 4; ++mt) {
            a[mt][0] = dp[(16 * mt) * DSTRIDE];
            a[mt][1] = dp[(16 * mt + 8) * DSTRIDE];
            a[mt][2] = dp[(16 * mt) * DSTRIDE + 4];
            a[mt][3] = dp[(16 * mt + 8) * DSTRIDE + 4];
        }
        const uint4* bp = Bg + s * 256 + chalf * 4 * 32 + lane;
        #pragma unroll
        for (int p = 0; p < 4; ++p) {
            uint4 bb = bp[p * 32];
            #pragma unroll
            for (int mt = 0; mt < 4; ++mt) {
                mma_tf32(d[mt][2 * p],     a[mt][0], a[mt][1], a[mt][2], a[mt][3], bb.x, bb.y);
                mma_tf32(d[mt][2 * p + 1], a[mt][0], a[mt][1], a[mt][2], a[mt][3], bb.z, bb.w);
            }
        }
    }

    // max over valid t (this warp covers all t for its channels)
    #pragma unroll
    for (int nt = 0; nt < 8; ++nt)
        #pragma unroll
        for (int r = 0; r < 2; ++r) {
            float m = -1e30f;
            #pragma unroll
            for (int mt = 0; mt < 4; ++mt)
                #pragma unroll
                for (int rr = 0; rr < 2; ++rr) {
                    int tl = 16 * mt + (lane >> 2) + 8 * rr;
                    if (tl < T) m = fmaxf(m, d[mt][nt][2 * rr + r]);
                }
            m = fmaxf(m, __shfl_xor_sync(0xFFFFFFFFu, m, 4));
            m = fmaxf(m, __shfl_xor_sync(0xFFFFFFFFu, m, 8));
            m = fmaxf(m, __shfl_xor_sync(0xFFFFFFFFu, m, 16));
            if (lane < 4) {
                int c = (chalf * 8 + nt) * 8 + 2 * lane + r;
                feats[kidx * 128 + c] = fmaxf(m + bias[c], 0.0f);
            }
        }
}

__global__ __launch_bounds__(128) void conv_mma_kernel(
    const int* __restrict__ news_words,
    const float* __restrict__ b3, const float* __restrict__ b4, const float* __restrict__ b5,
    const float* __restrict__ fcT, const float* __restrict__ fc_b,
    float* __restrict__ out)
{
    extern __shared__ uint32_t cs[];
    uint32_t* doc   = cs;                               // 2*DOCN u32 (tf32 bits)
    float*    feats = (float*)(cs + 2 * DOCN);          // 2*384
    int*      idx2  = (int*)(feats + 2 * 384);          // 128

    const int n0 = blockIdx.x * 2;
    const int tid = threadIdx.x;
    const int lane = tid & 31, warp = tid >> 5;
    const int news = warp >> 1, chalf = warp & 1;

    idx2[tid] = news_words[n0 * L_ + tid];              // 2*64 = 128 indices
    __syncthreads();

    #pragma unroll
    for (int b = 0; b < 2; ++b)
        #pragma unroll 4
        for (int l = 0; l < L_; ++l) {
            float v = g_word_embeds[idx2[b * L_ + l] * E_ + tid];
            doc[b * DOCN + l * DSTRIDE + tid] = f2tf32(v);
        }
    // zero pad rows 64..67 of each news
    for (int i = tid; i < 2 * 4 * DSTRIDE; i += 128) {
        int b = i / (4 * DSTRIDE);
        int rem = i - b * (4 * DSTRIDE);
        doc[b * DOCN + 64 * DSTRIDE + rem] = 0;
    }
    __syncthreads();

    const uint32_t* dbase = doc + news * DOCN;
    conv_mma_phase<3>(g_wmma + WOFF3, b3, dbase, feats + news * 384, 0, lane, chalf);
    conv_mma_phase<4>(g_wmma + WOFF4, b4, dbase, feats + news * 384, 1, lane, chalf);
    conv_mma_phase<5>(g_wmma + WOFF5, b5, dbase, feats + news * 384, 2, lane, chalf);
    __syncthreads();

    // FC epilogue: out[n, i] = fc_b[i] + feats . fcT[:, i]
    {
        const int i = tid;
        #pragma unroll
        for (int b = 0; b < 2; ++b) {
            float acc = fc_b[i];
            #pragma unroll 8
            for (int k = 0; k < 3 * C_; ++k) acc += feats[b * 384 + k] * fcT[k * E_ + i];
            out[(n0 + b) * E_ + i] = acc;
        }
    }
}

// ---------------- launch ----------------
extern "C" void kernel_launch(void* const* d_in, const int* in_sizes, int n_in,
                              void* d_out, int out_size) {
    const int*   word2news     = (const int*)d_in[0];
    const int*   word2news_len = (const int*)d_in[1];
    const int*   news_words    = (const int*)d_in[2];
    const float* table         = (const float*)d_in[3];
    const float* in_w          = (const float*)d_in[4];
    const float* in_b          = (const float*)d_in[5];
    const float* out_w         = (const float*)d_in[6];
    const float* out_b         = (const float*)d_in[7];
    const float* w3            = (const float*)d_in[8];
    const float* b3            = (const float*)d_in[9];
    const float* w4            = (const float*)d_in[10];
    const float* b4            = (const float*)d_in[11];
    const float* w5            = (const float*)d_in[12];
    const float* b5            = (const float*)d_in[13];
    const float* fc_w          = (const float*)d_in[14];
    const float* fc_b          = (const float*)d_in[15];
    float* out = (float*)d_out;

    float *wqT, *wvT, *woT, *fcT;
    cudaGetSymbolAddress((void**)&wqT, g_wqT);
    cudaGetSymbolAddress((void**)&wvT, g_wvT);
    cudaGetSymbolAddress((void**)&woT, g_woT);
    cudaGetSymbolAddress((void**)&fcT, g_fcT);

    const int word_smem = (int)sizeof(WSmem);
    const int conv_smem = (2 * DOCN + 2 * 384 + 128) * 4;   // ~75 KB
    cudaFuncSetAttribute(word_embed_kernel,
                         cudaFuncAttributeMaxDynamicSharedMemorySize, word_smem);
    cudaFuncSetAttribute(conv_mma_kernel,
                         cudaFuncAttributeMaxDynamicSharedMemorySize, conv_smem);

    prep_a_kernel<<<(PREPA_TOTAL + 255) / 256, 256>>>(in_w, out_w, fc_w);
    prep_b_kernel<<<(PREPB_TOTAL + 255) / 256, 256>>>(w3, w4, w5);

    word_embed_kernel<<<V_ / WPB, 128, word_smem>>>(
        word2news, word2news_len, table, in_w, in_b, out_b, wqT, wvT, woT);

    conv_mma_kernel<<<N_ / 2, 128, conv_smem>>>(news_words, b3, b4, b5, fcT, fc_b, out);
}

// round 8
// speedup vs baseline: 1.0970x; 1.0970x over previous
#include <cuda_runtime.h>
#include <cuda_bf16.h>
#include <cstdint>

// Problem constants
#define V_  20000
#define M_  32
#define E_  128
#define H_  4
#define N_  8192
#define L_  64
#define C_  128
#define WPB 2          // words per block in word_embed kernel

// conv doc tile geometry (unswizzled, bank-conflict-free stride)
#define DSTRIDE 132            // floats per row (132 mod 32 = 4 -> conflict-free)
#define DOCROWS 68             // 64 + 4 pad rows (pads only feed discarded t)
#define DOCN   (DOCROWS * DSTRIDE)

// ---------------- device scratch (no allocations allowed) ----------------
__device__ float g_word_embeds[V_ * E_];          // [V,E]
__device__ float g_wqT[E_ * E_];                  // [e][i] = Wq[i][e]
__device__ float g_wvT[E_ * E_];                  // [e][i] = Wv[i][e]
__device__ float g_woT[E_ * E_];                  // [e][i] = out_w[i][e]
__device__ float g_fcT[3 * C_ * E_];              // [i][c] = fc_w[c][i]
// fragment-packed tf32 conv weights: per kstep s: 8 ntile-pairs x 32 lanes x uint4
__device__ uint4 g_wmma[49152];
#define WOFF3 0
#define WOFF4 12288
#define WOFF5 28672

// ---------------- tf32 helpers ----------------
__device__ __forceinline__ uint32_t f2tf32(float x) {
    uint32_t u;
    asm("cvt.rna.tf32.f32 %0, %1;" : "=r"(u) : "f"(x));
    return u;
}

__device__ __forceinline__ void mma_tf32(float* d,
                                         uint32_t a0, uint32_t a1, uint32_t a2, uint32_t a3,
                                         uint32_t b0, uint32_t b1) {
    asm volatile(
        "mma.sync.aligned.m16n8k8.row.col.f32.tf32.tf32.f32 "
        "{%0,%1,%2,%3}, {%4,%5,%6,%7}, {%8,%9}, {%0,%1,%2,%3};"
        : "+f"(d[0]), "+f"(d[1]), "+f"(d[2]), "+f"(d[3])
        : "r"(a0), "r"(a1), "r"(a2), "r"(a3), "r"(b0), "r"(b1));
}

// ---------------- prep kernels (three launches: word lands at ncu index 3) --
#define PSEG0 (E_ * E_)
#define PSEG3 (3 * C_ * E_)
#define PW3   (3 * 16 * 1024)
#define PW4   (4 * 16 * 1024)
#define PW5   (5 * 16 * 1024)
#define PREPW_TOTAL (PW3 + PW4 + PW5)

__global__ void prep_t_kernel(const float* __restrict__ in_w,
                              const float* __restrict__ out_w) {
    int idx = blockIdx.x * blockDim.x + threadIdx.x;
    if (idx >= 3 * PSEG0) return;
    int seg = idx / PSEG0;
    int r = idx - seg * PSEG0;
    int e = r >> 7, i = r & 127;
    if (seg == 0)      g_wqT[r] = in_w[i * E_ + e];
    else if (seg == 1) g_wvT[r] = in_w[2 * E_ * E_ + i * E_ + e];
    else               g_woT[r] = out_w[i * E_ + e];
}

__global__ void prep_fc_kernel(const float* __restrict__ fc_w) {
    int idx = blockIdx.x * blockDim.x + threadIdx.x;
    if (idx >= PSEG3) return;
    int i = idx >> 7, c = idx & 127;
    g_fcT[idx] = fc_w[c * (3 * C_) + i];
}

__device__ __forceinline__ void prep_wmma_one(const float* __restrict__ w, int K,
                                              int dst_off_u4, int idx) {
    int s    = idx >> 10;
    int rem  = idx & 1023;
    int p    = rem >> 7;
    int lane = (rem >> 2) & 31;
    int q    = rem & 3;
    int j  = s >> 4, ec = s & 15;
    int nt = 2 * p + (q >> 1);
    int kk = (lane & 3) + 4 * (q & 1);
    int c  = nt * 8 + (lane >> 2);
    int e  = ec * 8 + kk;
    float v = w[(c * E_ + e) * K + j];
    reinterpret_cast<uint32_t*>(g_wmma)[dst_off_u4 * 4 + idx] = f2tf32(v);
}

__global__ void prep_w_kernel(const float* __restrict__ w3,
                              const float* __restrict__ w4,
                              const float* __restrict__ w5) {
    int idx = blockIdx.x * blockDim.x + threadIdx.x;
    if (idx >= PREPW_TOTAL) return;
    if (idx < PW3) { prep_wmma_one(w3, 3, WOFF3, idx); return; }
    idx -= PW3;
    if (idx < PW4) { prep_wmma_one(w4, 4, WOFF4, idx); return; }
    idx -= PW4;
    prep_wmma_one(w5, 5, WOFF5, idx);
}

// ---------------- word embedding kernel: 2 words per block ----------------
struct WSmem {
    float ctx[WPB][M_][E_ + 1];
    float q[WPB][E_];
    float qh[WPB][E_];
    float g[WPB][H_][E_];
    float ch[WPB][H_][E_];
    float o[WPB][E_];
    float attn[WPB][H_][M_];
    float cb[WPB][H_];
    int   idx[WPB][M_];
    int   len[WPB];
};

__global__ __launch_bounds__(128) void word_embed_kernel(
    const int* __restrict__ word2news, const int* __restrict__ word2news_len,
    const float* __restrict__ table,
    const float* __restrict__ in_w, const float* __restrict__ in_b,
    const float* __restrict__ out_b,
    const float* __restrict__ wqT, const float* __restrict__ wvT,
    const float* __restrict__ woT)
{
    extern __shared__ char smem_raw[];
    WSmem& s = *reinterpret_cast<WSmem*>(smem_raw);

    const int v0 = blockIdx.x * WPB;
    const int tid = threadIdx.x;
    const int lane = tid & 31, warp = tid >> 5;

    if (tid < WPB * M_) {
        int w = tid >> 5, m = tid & 31;
        s.idx[w][m] = word2news[(v0 + w) * M_ + m];
    }
    if (tid < WPB) s.len[tid] = word2news_len[v0 + tid];
    __syncthreads();

    // gather ctx rows via float4: warp handles row m = m4*4 + warp (m4 = 0..7)
    #pragma unroll
    for (int w = 0; w < WPB; ++w)
        #pragma unroll
        for (int m4 = 0; m4 < 8; ++m4) {
            int m = m4 * 4 + warp;
            float4 v = *reinterpret_cast<const float4*>(
                &table[s.idx[w][m] * E_ + lane * 4]);
            s.ctx[w][m][lane * 4 + 0] = v.x;
            s.ctx[w][m][lane * 4 + 1] = v.y;
            s.ctx[w][m][lane * 4 + 2] = v.z;
            s.ctx[w][m][lane * 4 + 3] = v.w;
        }
    __syncthreads();

    // masked mean query: branchless, fully unrolled (no serial var-length chain)
    #pragma unroll
    for (int w = 0; w < WPB; ++w) {
        int len = s.len[w];
        float inv = 1.0f / (float)(len > 0 ? len : 1);
        float a = 0.0f;
        #pragma unroll
        for (int m = 0; m < M_; ++m) {
            float val = s.ctx[w][m][tid];
            a += (m < len) ? val : 0.0f;
        }
        s.q[w][tid] = a * inv;
    }
    __syncthreads();

    // qh = q @ Wq^T + bq
    {
        float acc[WPB];
        #pragma unroll
        for (int w = 0; w < WPB; ++w) acc[w] = 0.0f;
        #pragma unroll 8
        for (int e = 0; e < E_; ++e) {
            float wq = wqT[e * E_ + tid];
            #pragma unroll
            for (int w = 0; w < WPB; ++w) acc[w] += s.q[w][e] * wq;
        }
        float bq = in_b[tid];
        #pragma unroll
        for (int w = 0; w < WPB; ++w) s.qh[w][tid] = acc[w] + bq;
    }
    __syncthreads();

    // g_h[e] = sum_d qh[h*32+d] * Wk[h*32+d][e]
    #pragma unroll
    for (int h = 0; h < H_; ++h) {
        float acc[WPB];
        #pragma unroll
        for (int w = 0; w < WPB; ++w) acc[w] = 0.0f;
        #pragma unroll 8
        for (int d = 0; d < 32; ++d) {
            float wk = in_w[(E_ + h * 32 + d) * E_ + tid];
            #pragma unroll
            for (int w = 0; w < WPB; ++w) acc[w] += s.qh[w][h * 32 + d] * wk;
        }
        #pragma unroll
        for (int w = 0; w < WPB; ++w) s.g[w][h][tid] = acc[w];
    }
    if (tid < WPB * H_) {
        int w = tid >> 2, h = tid & 3;
        float c = 0.0f;
        #pragma unroll 8
        for (int d = 0; d < 32; ++d) c += s.qh[w][h * 32 + d] * in_b[E_ + h * 32 + d];
        s.cb[w][h] = c;
    }
    __syncthreads();

    // scores + per-head warp softmax: thread = (h = warp, m = lane)
    {
        const int h = warp, m = lane;
        #pragma unroll
        for (int w = 0; w < WPB; ++w) {
            float sc = s.cb[w][h];
            #pragma unroll 8
            for (int e = 0; e < E_; ++e) sc += s.ctx[w][m][e] * s.g[w][h][e];
            sc *= 0.17677669529663688f;               // 1/sqrt(32)
            if (m >= s.len[w]) sc = -1e30f;
            float wm = sc;
            #pragma unroll
            for (int o = 16; o; o >>= 1) wm = fmaxf(wm, __shfl_xor_sync(0xFFFFFFFFu, wm, o));
            float p = __expf(sc - wm);
            float ps = p;
            #pragma unroll
            for (int o = 16; o; o >>= 1) ps += __shfl_xor_sync(0xFFFFFFFFu, ps, o);
            s.attn[w][h][m] = p / ps;
        }
    }
    __syncthreads();

    // ch_h[e] = sum_m attn[h,m]*ctx[m][e]
    #pragma unroll
    for (int w = 0; w < WPB; ++w)
        #pragma unroll
        for (int h = 0; h < H_; ++h) {
            float c = 0.0f;
            #pragma unroll 8
            for (int m = 0; m < M_; ++m) c += s.attn[w][h][m] * s.ctx[w][m][tid];
            s.ch[w][h][tid] = c;
        }
    __syncthreads();

    // o[i] = ch_{h(i)} . Wv[i] + bv[i]
    {
        const int h = warp;
        float acc[WPB];
        #pragma unroll
        for (int w = 0; w < WPB; ++w) acc[w] = 0.0f;
        #pragma unroll 8
        for (int e = 0; e < E_; ++e) {
            float wv = wvT[e * E_ + tid];
            #pragma unroll
            for (int w = 0; w < WPB; ++w) acc[w] += s.ch[w][h][e] * wv;
        }
        float bv = in_b[2 * E_ + tid];
        #pragma unroll
        for (int w = 0; w < WPB; ++w) s.o[w][tid] = acc[w] + bv;
    }
    __syncthreads();

    // out proj
    {
        float acc[WPB];
        #pragma unroll
        for (int w = 0; w < WPB; ++w) acc[w] = 0.0f;
        #pragma unroll 8
        for (int e = 0; e < E_; ++e) {
            float wo = woT[e * E_ + tid];
            #pragma unroll
            for (int w = 0; w < WPB; ++w) acc[w] += s.o[w][e] * wo;
        }
        float ob = out_b[tid];
        #pragma unroll
        for (int w = 0; w < WPB; ++w)
            g_word_embeds[(v0 + w) * E_ + tid] = (s.len[w] > 0) ? (acc[w] + ob) : 0.0f;
    }
}

// ---------------- conv (tf32 mma) + maxpool + FC: 2 news per block ----------
// R4 layout (best known): warp = (news = w>>1, t-half = w&1), 16 ntiles/warp.
template <int K>
__device__ __forceinline__ void conv_mma_phase(
    const uint4* __restrict__ B, const float* __restrict__ bias,
    const uint32_t* __restrict__ doc, float* pp, float* feats, int kidx, int tid)
{
    const int lane = tid & 31, warp = tid >> 5;
    const int news = warp >> 1;
    const int tb = (warp & 1) * 32;
    const uint32_t* dbase = doc + news * DOCN;

    float d[2][16][4];
    #pragma unroll
    for (int mt = 0; mt < 2; ++mt)
        #pragma unroll
        for (int nt = 0; nt < 16; ++nt)
            #pragma unroll
            for (int k = 0; k < 4; ++k) d[mt][nt][k] = 0.0f;

    for (int s = 0; s < K * 16; ++s) {
        const int j = s >> 4, ec = s & 15;
        const uint32_t* dp = dbase + (tb + j + (lane >> 2)) * DSTRIDE + ec * 8 + (lane & 3);
        uint32_t a[2][4];
        #pragma unroll
        for (int mt = 0; mt < 2; ++mt) {
            a[mt][0] = dp[(16 * mt) * DSTRIDE];
            a[mt][1] = dp[(16 * mt + 8) * DSTRIDE];
            a[mt][2] = dp[(16 * mt) * DSTRIDE + 4];
            a[mt][3] = dp[(16 * mt + 8) * DSTRIDE + 4];
        }
        const uint4* bp = B + s * 256 + lane;
        #pragma unroll
        for (int p = 0; p < 8; ++p) {
            uint4 bb = bp[p * 32];
            mma_tf32(d[0][2 * p],     a[0][0], a[0][1], a[0][2], a[0][3], bb.x, bb.y);
            mma_tf32(d[1][2 * p],     a[1][0], a[1][1], a[1][2], a[1][3], bb.x, bb.y);
            mma_tf32(d[0][2 * p + 1], a[0][0], a[0][1], a[0][2], a[0][3], bb.z, bb.w);
            mma_tf32(d[1][2 * p + 1], a[1][0], a[1][1], a[1][2], a[1][3], bb.z, bb.w);
        }
    }

    // max over valid t within warp, then across lane-groups
    constexpr int T = L_ - K + 1;
    #pragma unroll
    for (int nt = 0; nt < 16; ++nt)
        #pragma unroll
        for (int r = 0; r < 2; ++r) {
            float m = -1e30f;
            #pragma unroll
            for (int mt = 0; mt < 2; ++mt)
                #pragma unroll
                for (int rr = 0; rr < 2; ++rr) {
                    int tl = tb + 16 * mt + (lane >> 2) + 8 * rr;
                    if (tl < T) m = fmaxf(m, d[mt][nt][2 * rr + r]);
                }
            m = fmaxf(m, __shfl_xor_sync(0xFFFFFFFFu, m, 4));
            m = fmaxf(m, __shfl_xor_sync(0xFFFFFFFFu, m, 8));
            m = fmaxf(m, __shfl_xor_sync(0xFFFFFFFFu, m, 16));
            if (lane < 4) pp[warp * 128 + nt * 8 + 2 * lane + r] = m;
        }
    __syncthreads();
    {
        int c = tid;
        #pragma unroll
        for (int b = 0; b < 2; ++b) {
            float v = fmaxf(pp[(2 * b) * 128 + c], pp[(2 * b + 1) * 128 + c]);
            feats[b * 384 + kidx * 128 + c] = fmaxf(v + bias[c], 0.0f);
        }
    }
    __syncthreads();
}

__global__ __launch_bounds__(128) void conv_mma_kernel(
    const int* __restrict__ news_words,
    const float* __restrict__ b3, const float* __restrict__ b4, const float* __restrict__ b5,
    const float* __restrict__ fcT, const float* __restrict__ fc_b,
    float* __restrict__ out)
{
    extern __shared__ uint32_t cs[];
    uint32_t* doc   = cs;                               // 2*DOCN u32 (tf32 bits)
    float*    pp    = (float*)(cs + 2 * DOCN);          // 4*128
    float*    feats = pp + 512;                         // 2*384
    int*      idx2  = (int*)(feats + 768);              // 128

    const int n0 = blockIdx.x * 2;
    const int tid = threadIdx.x;

    idx2[tid] = news_words[n0 * L_ + tid];              // 2*64 = 128 indices
    __syncthreads();

    #pragma unroll
    for (int b = 0; b < 2; ++b)
        #pragma unroll 4
        for (int l = 0; l < L_; ++l) {
            float v = g_word_embeds[idx2[b * L_ + l] * E_ + tid];
            doc[b * DOCN + l * DSTRIDE + tid] = f2tf32(v);
        }
    // zero pad rows 64..67 of each news
    for (int i = tid; i < 2 * 4 * DSTRIDE; i += 128) {
        int b = i / (4 * DSTRIDE);
        int rem = i - b * (4 * DSTRIDE);
        doc[b * DOCN + 64 * DSTRIDE + rem] = 0;
    }
    __syncthreads();

    conv_mma_phase<3>(g_wmma + WOFF3, b3, doc, pp, feats, 0, tid);
    conv_mma_phase<4>(g_wmma + WOFF4, b4, doc, pp, feats, 1, tid);
    conv_mma_phase<5>(g_wmma + WOFF5, b5, doc, pp, feats, 2, tid);

    // FC epilogue: out[n, i] = fc_b[i] + feats . fcT[:, i]
    const int i = tid;
    #pragma unroll
    for (int b = 0; b < 2; ++b) {
        float acc = fc_b[i];
        #pragma unroll 8
        for (int k = 0; k < 3 * C_; ++k) acc += feats[b * 384 + k] * fcT[k * E_ + i];
        out[(n0 + b) * E_ + i] = acc;
    }
}

// ---------------- launch ----------------
extern "C" void kernel_launch(void* const* d_in, const int* in_sizes, int n_in,
                              void* d_out, int out_size) {
    const int*   word2news     = (const int*)d_in[0];
    const int*   word2news_len = (const int*)d_in[1];
    const int*   news_words    = (const int*)d_in[2];
    const float* table         = (const float*)d_in[3];
    const float* in_w          = (const float*)d_in[4];
    const float* in_b          = (const float*)d_in[5];
    const float* out_w         = (const float*)d_in[6];
    const float* out_b         = (const float*)d_in[7];
    const float* w3            = (const float*)d_in[8];
    const float* b3            = (const float*)d_in[9];
    const float* w4            = (const float*)d_in[10];
    const float* b4            = (const float*)d_in[11];
    const float* w5            = (const float*)d_in[12];
    const float* b5            = (const float*)d_in[13];
    const float* fc_w          = (const float*)d_in[14];
    const float* fc_b          = (const float*)d_in[15];
    float* out = (float*)d_out;

    float *wqT, *wvT, *woT, *fcT;
    cudaGetSymbolAddress((void**)&wqT, g_wqT);
    cudaGetSymbolAddress((void**)&wvT, g_wvT);
    cudaGetSymbolAddress((void**)&woT, g_woT);
    cudaGetSymbolAddress((void**)&fcT, g_fcT);

    const int word_smem = (int)sizeof(WSmem);
    const int conv_smem = (2 * DOCN + 512 + 768 + 128) * 4;   // ~77 KB
    cudaFuncSetAttribute(word_embed_kernel,
                         cudaFuncAttributeMaxDynamicSharedMemorySize, word_smem);
    cudaFuncSetAttribute(conv_mma_kernel,
                         cudaFuncAttributeMaxDynamicSharedMemorySize, conv_smem);

    prep_t_kernel<<<(3 * PSEG0 + 255) / 256, 256>>>(in_w, out_w);
    prep_fc_kernel<<<(PSEG3 + 255) / 256, 256>>>(fc_w);
    prep_w_kernel<<<(PREPW_TOTAL + 255) / 256, 256>>>(w3, w4, w5);

    word_embed_kernel<<<V_ / WPB, 128, word_smem>>>(
        word2news, word2news_len, table, in_w, in_b, out_b, wqT, wvT, woT);

    conv_mma_kernel<<<N_ / 2, 128, conv_smem>>>(news_words, b3, b4, b5, fcT, fc_b, out);
}

// round 9
// speedup vs baseline: 1.3548x; 1.2350x over previous
#include <cuda_runtime.h>
#include <cuda_bf16.h>
#include <cstdint>

// Problem constants
#define V_  20000
#define M_  32
#define E_  128
#define H_  4
#define N_  8192
#define L_  64
#define C_  128
#define WPB 2          // words per block in word_embed kernel

// conv doc tile geometry (unswizzled, bank-conflict-free stride)
#define DSTRIDE 132            // floats per row (132 mod 32 = 4 -> conflict-free)
#define DOCROWS 68             // 64 + 4 pad rows (pads only feed discarded t)
#define DOCN   (DOCROWS * DSTRIDE)

// ---------------- device scratch (no allocations allowed) ----------------
__device__ float g_word_embeds[V_ * E_];          // [V,E]
__device__ float g_wqT[E_ * E_];                  // [e][i] = Wq[i][e]
__device__ float g_wvT[E_ * E_];                  // [e][i] = Wv[i][e]
__device__ float g_woT[E_ * E_];                  // [e][i] = out_w[i][e]
__device__ float g_fcT[3 * C_ * E_];              // [i][c] = fc_w[c][i]
// fragment-packed tf32 conv weights (+256 pad uint4 for unguarded prefetch)
__device__ uint4 g_wmma[49152 + 256];
#define WOFF3 0
#define WOFF4 12288
#define WOFF5 28672

// ---------------- tf32 helpers ----------------
__device__ __forceinline__ uint32_t f2tf32(float x) {
    uint32_t u;
    asm("cvt.rna.tf32.f32 %0, %1;" : "=r"(u) : "f"(x));
    return u;
}

__device__ __forceinline__ void mma_tf32(float* d,
                                         uint32_t a0, uint32_t a1, uint32_t a2, uint32_t a3,
                                         uint32_t b0, uint32_t b1) {
    asm volatile(
        "mma.sync.aligned.m16n8k8.row.col.f32.tf32.tf32.f32 "
        "{%0,%1,%2,%3}, {%4,%5,%6,%7}, {%8,%9}, {%0,%1,%2,%3};"
        : "+f"(d[0]), "+f"(d[1]), "+f"(d[2]), "+f"(d[3])
        : "r"(a0), "r"(a1), "r"(a2), "r"(a3), "r"(b0), "r"(b1));
}

// ---------------- prep kernels (three launches: word lands at ncu index 3) --
#define PSEG0 (E_ * E_)
#define PSEG3 (3 * C_ * E_)
#define PW3   (3 * 16 * 1024)
#define PW4   (4 * 16 * 1024)
#define PW5   (5 * 16 * 1024)
#define PREPW_TOTAL (PW3 + PW4 + PW5)

__global__ void prep_t_kernel(const float* __restrict__ in_w,
                              const float* __restrict__ out_w) {
    int idx = blockIdx.x * blockDim.x + threadIdx.x;
    if (idx >= 3 * PSEG0) return;
    int seg = idx / PSEG0;
    int r = idx - seg * PSEG0;
    int e = r >> 7, i = r & 127;
    if (seg == 0)      g_wqT[r] = in_w[i * E_ + e];
    else if (seg == 1) g_wvT[r] = in_w[2 * E_ * E_ + i * E_ + e];
    else               g_woT[r] = out_w[i * E_ + e];
}

__global__ void prep_fc_kernel(const float* __restrict__ fc_w) {
    int idx = blockIdx.x * blockDim.x + threadIdx.x;
    if (idx >= PSEG3) return;
    int i = idx >> 7, c = idx & 127;
    g_fcT[idx] = fc_w[c * (3 * C_) + i];
}

__device__ __forceinline__ void prep_wmma_one(const float* __restrict__ w, int K,
                                              int dst_off_u4, int idx) {
    int s    = idx >> 10;
    int rem  = idx & 1023;
    int p    = rem >> 7;
    int lane = (rem >> 2) & 31;
    int q    = rem & 3;
    int j  = s >> 4, ec = s & 15;
    int nt = 2 * p + (q >> 1);
    int kk = (lane & 3) + 4 * (q & 1);
    int c  = nt * 8 + (lane >> 2);
    int e  = ec * 8 + kk;
    float v = w[(c * E_ + e) * K + j];
    reinterpret_cast<uint32_t*>(g_wmma)[dst_off_u4 * 4 + idx] = f2tf32(v);
}

__global__ void prep_w_kernel(const float* __restrict__ w3,
                              const float* __restrict__ w4,
                              const float* __restrict__ w5) {
    int idx = blockIdx.x * blockDim.x + threadIdx.x;
    if (idx >= PREPW_TOTAL) return;
    if (idx < PW3) { prep_wmma_one(w3, 3, WOFF3, idx); return; }
    idx -= PW3;
    if (idx < PW4) { prep_wmma_one(w4, 4, WOFF4, idx); return; }
    idx -= PW4;
    prep_wmma_one(w5, 5, WOFF5, idx);
}

// ---------------- word embedding kernel: 2 words per block ----------------
struct WSmem {
    float ctx[WPB][M_][E_ + 1];
    float q[WPB][E_];
    float qh[WPB][E_];
    float g[WPB][H_][E_];
    float ch[WPB][H_][E_];
    float o[WPB][E_];
    float attn[WPB][H_][M_];
    float cb[WPB][H_];
    int   idx[WPB][M_];
    int   len[WPB];
};

__global__ __launch_bounds__(128) void word_embed_kernel(
    const int* __restrict__ word2news, const int* __restrict__ word2news_len,
    const float* __restrict__ table,
    const float* __restrict__ in_w, const float* __restrict__ in_b,
    const float* __restrict__ out_b,
    const float* __restrict__ wqT, const float* __restrict__ wvT,
    const float* __restrict__ woT)
{
    extern __shared__ char smem_raw[];
    WSmem& s = *reinterpret_cast<WSmem*>(smem_raw);

    const int v0 = blockIdx.x * WPB;
    const int tid = threadIdx.x;
    const int lane = tid & 31, warp = tid >> 5;

    if (tid < WPB * M_) {
        int w = tid >> 5, m = tid & 31;
        s.idx[w][m] = word2news[(v0 + w) * M_ + m];
    }
    if (tid < WPB) s.len[tid] = word2news_len[v0 + tid];
    __syncthreads();

    // gather ctx rows via float4: warp handles row m = m4*4 + warp (m4 = 0..7)
    #pragma unroll
    for (int w = 0; w < WPB; ++w)
        #pragma unroll
        for (int m4 = 0; m4 < 8; ++m4) {
            int m = m4 * 4 + warp;
            float4 v = *reinterpret_cast<const float4*>(
                &table[s.idx[w][m] * E_ + lane * 4]);
            s.ctx[w][m][lane * 4 + 0] = v.x;
            s.ctx[w][m][lane * 4 + 1] = v.y;
            s.ctx[w][m][lane * 4 + 2] = v.z;
            s.ctx[w][m][lane * 4 + 3] = v.w;
        }
    __syncthreads();

    // masked mean query: branchless, fully unrolled
    #pragma unroll
    for (int w = 0; w < WPB; ++w) {
        int len = s.len[w];
        float inv = 1.0f / (float)(len > 0 ? len : 1);
        float a = 0.0f;
        #pragma unroll
        for (int m = 0; m < M_; ++m) {
            float val = s.ctx[w][m][tid];
            a += (m < len) ? val : 0.0f;
        }
        s.q[w][tid] = a * inv;
    }
    __syncthreads();

    // qh = q @ Wq^T + bq
    {
        float acc[WPB];
        #pragma unroll
        for (int w = 0; w < WPB; ++w) acc[w] = 0.0f;
        #pragma unroll 8
        for (int e = 0; e < E_; ++e) {
            float wq = wqT[e * E_ + tid];
            #pragma unroll
            for (int w = 0; w < WPB; ++w) acc[w] += s.q[w][e] * wq;
        }
        float bq = in_b[tid];
        #pragma unroll
        for (int w = 0; w < WPB; ++w) s.qh[w][tid] = acc[w] + bq;
    }
    __syncthreads();

    // g_h[e] = sum_d qh[h*32+d] * Wk[h*32+d][e]
    #pragma unroll
    for (int h = 0; h < H_; ++h) {
        float acc[WPB];
        #pragma unroll
        for (int w = 0; w < WPB; ++w) acc[w] = 0.0f;
        #pragma unroll 8
        for (int d = 0; d < 32; ++d) {
            float wk = in_w[(E_ + h * 32 + d) * E_ + tid];
            #pragma unroll
            for (int w = 0; w < WPB; ++w) acc[w] += s.qh[w][h * 32 + d] * wk;
        }
        #pragma unroll
        for (int w = 0; w < WPB; ++w) s.g[w][h][tid] = acc[w];
    }
    if (tid < WPB * H_) {
        int w = tid >> 2, h = tid & 3;
        float c = 0.0f;
        #pragma unroll 8
        for (int d = 0; d < 32; ++d) c += s.qh[w][h * 32 + d] * in_b[E_ + h * 32 + d];
        s.cb[w][h] = c;
    }
    __syncthreads();

    // scores + per-head warp softmax: thread = (h = warp, m = lane)
    {
        const int h = warp, m = lane;
        #pragma unroll
        for (int w = 0; w < WPB; ++w) {
            float sc = s.cb[w][h];
            #pragma unroll 8
            for (int e = 0; e < E_; ++e) sc += s.ctx[w][m][e] * s.g[w][h][e];
            sc *= 0.17677669529663688f;               // 1/sqrt(32)
            if (m >= s.len[w]) sc = -1e30f;
            float wm = sc;
            #pragma unroll
            for (int o = 16; o; o >>= 1) wm = fmaxf(wm, __shfl_xor_sync(0xFFFFFFFFu, wm, o));
            float p = __expf(sc - wm);
            float ps = p;
            #pragma unroll
            for (int o = 16; o; o >>= 1) ps += __shfl_xor_sync(0xFFFFFFFFu, ps, o);
            s.attn[w][h][m] = p / ps;
        }
    }
    __syncthreads();

    // ch_h[e] = sum_m attn[h,m]*ctx[m][e]
    #pragma unroll
    for (int w = 0; w < WPB; ++w)
        #pragma unroll
        for (int h = 0; h < H_; ++h) {
            float c = 0.0f;
            #pragma unroll 8
            for (int m = 0; m < M_; ++m) c += s.attn[w][h][m] * s.ctx[w][m][tid];
            s.ch[w][h][tid] = c;
        }
    __syncthreads();

    // o[i] = ch_{h(i)} . Wv[i] + bv[i]
    {
        const int h = warp;
        float acc[WPB];
        #pragma unroll
        for (int w = 0; w < WPB; ++w) acc[w] = 0.0f;
        #pragma unroll 8
        for (int e = 0; e < E_; ++e) {
            float wv = wvT[e * E_ + tid];
            #pragma unroll
            for (int w = 0; w < WPB; ++w) acc[w] += s.ch[w][h][e] * wv;
        }
        float bv = in_b[2 * E_ + tid];
        #pragma unroll
        for (int w = 0; w < WPB; ++w) s.o[w][tid] = acc[w] + bv;
    }
    __syncthreads();

    // out proj
    {
        float acc[WPB];
        #pragma unroll
        for (int w = 0; w < WPB; ++w) acc[w] = 0.0f;
        #pragma unroll 8
        for (int e = 0; e < E_; ++e) {
            float wo = woT[e * E_ + tid];
            #pragma unroll
            for (int w = 0; w < WPB; ++w) acc[w] += s.o[w][e] * wo;
        }
        float ob = out_b[tid];
        #pragma unroll
        for (int w = 0; w < WPB; ++w)
            g_word_embeds[(v0 + w) * E_ + tid] = (s.len[w] > 0) ? (acc[w] + ob) : 0.0f;
    }
}

// ---------------- conv (tf32 mma) + maxpool + FC: 2 news per block ----------
// R4 layout + B register ping-pong pipeline: B for step s+1 is in flight while
// the 32 MMAs of step s execute (hides the ~240cyc L2 latency at 2 warps/SMSP).
#define CONV_STEP(sv, buf)                                                        \
    do {                                                                          \
        const int j_ = (sv) >> 4, ec_ = (sv) & 15;                                \
        const uint32_t* dp = dbase + (tb + j_ + (lane >> 2)) * DSTRIDE            \
                             + ec_ * 8 + (lane & 3);                              \
        uint32_t a0 = dp[0],               a1 = dp[8 * DSTRIDE];                  \
        uint32_t a2 = dp[4],               a3 = dp[8 * DSTRIDE + 4];              \
        uint32_t a4 = dp[16 * DSTRIDE],    a5 = dp[24 * DSTRIDE];                 \
        uint32_t a6 = dp[16 * DSTRIDE + 4], a7 = dp[24 * DSTRIDE + 4];            \
        _Pragma("unroll")                                                         \
        for (int p = 0; p < 8; ++p) {                                             \
            uint4 bb = (buf)[p];                                                  \
            mma_tf32(d[0][2 * p],     a0, a1, a2, a3, bb.x, bb.y);                \
            mma_tf32(d[1][2 * p],     a4, a5, a6, a7, bb.x, bb.y);                \
            mma_tf32(d[0][2 * p + 1], a0, a1, a2, a3, bb.z, bb.w);                \
            mma_tf32(d[1][2 * p + 1], a4, a5, a6, a7, bb.z, bb.w);                \
        }                                                                         \
    } while (0)

template <int K>
__device__ __forceinline__ void conv_mma_phase(
    const uint4* __restrict__ B, const float* __restrict__ bias,
    const uint32_t* __restrict__ doc, float* pp, float* feats, int kidx, int tid)
{
    const int lane = tid & 31, warp = tid >> 5;
    const int news = warp >> 1;
    const int tb = (warp & 1) * 32;
    const uint32_t* dbase = doc + news * DOCN;
    constexpr int S = K * 16;                  // even

    float d[2][16][4];
    #pragma unroll
    for (int mt = 0; mt < 2; ++mt)
        #pragma unroll
        for (int nt = 0; nt < 16; ++nt)
            #pragma unroll
            for (int k = 0; k < 4; ++k) d[mt][nt][k] = 0.0f;

    const uint4* bp = B + lane;
    uint4 bufA[8], bufB[8];
    #pragma unroll
    for (int p = 0; p < 8; ++p) bufA[p] = bp[p * 32];          // step 0

    for (int s = 0; s < S; s += 2) {
        #pragma unroll
        for (int p = 0; p < 8; ++p) bufB[p] = bp[(s + 1) * 256 + p * 32];
        CONV_STEP(s, bufA);
        #pragma unroll
        for (int p = 0; p < 8; ++p) bufA[p] = bp[(s + 2) * 256 + p * 32];  // padded
        CONV_STEP(s + 1, bufB);
    }

    // max over valid t within warp, then across lane-groups
    constexpr int T = L_ - K + 1;
    #pragma unroll
    for (int nt = 0; nt < 16; ++nt)
        #pragma unroll
        for (int r = 0; r < 2; ++r) {
            float m = -1e30f;
            #pragma unroll
            for (int mt = 0; mt < 2; ++mt)
                #pragma unroll
                for (int rr = 0; rr < 2; ++rr) {
                    int tl = tb + 16 * mt + (lane >> 2) + 8 * rr;
                    if (tl < T) m = fmaxf(m, d[mt][nt][2 * rr + r]);
                }
            m = fmaxf(m, __shfl_xor_sync(0xFFFFFFFFu, m, 4));
            m = fmaxf(m, __shfl_xor_sync(0xFFFFFFFFu, m, 8));
            m = fmaxf(m, __shfl_xor_sync(0xFFFFFFFFu, m, 16));
            if (lane < 4) pp[warp * 128 + nt * 8 + 2 * lane + r] = m;
        }
    __syncthreads();
    {
        int c = tid;
        #pragma unroll
        for (int b = 0; b < 2; ++b) {
            float v = fmaxf(pp[(2 * b) * 128 + c], pp[(2 * b + 1) * 128 + c]);
            feats[b * 384 + kidx * 128 + c] = fmaxf(v + bias[c], 0.0f);
        }
    }
    __syncthreads();
}

__global__ __launch_bounds__(128) void conv_mma_kernel(
    const int* __restrict__ news_words,
    const float* __restrict__ b3, const float* __restrict__ b4, const float* __restrict__ b5,
    const float* __restrict__ fcT, const float* __restrict__ fc_b,
    float* __restrict__ out)
{
    extern __shared__ uint32_t cs[];
    uint32_t* doc   = cs;                               // 2*DOCN u32 (tf32 bits)
    float*    pp    = (float*)(cs + 2 * DOCN);          // 4*128
    float*    feats = pp + 512;                         // 2*384
    int*      idx2  = (int*)(feats + 768);              // 128

    const int n0 = blockIdx.x * 2;
    const int tid = threadIdx.x;

    idx2[tid] = news_words[n0 * L_ + tid];              // 2*64 = 128 indices
    __syncthreads();

    #pragma unroll
    for (int b = 0; b < 2; ++b)
        #pragma unroll 4
        for (int l = 0; l < L_; ++l) {
            float v = g_word_embeds[idx2[b * L_ + l] * E_ + tid];
            doc[b * DOCN + l * DSTRIDE + tid] = f2tf32(v);
        }
    // zero pad rows 64..67 of each news
    for (int i = tid; i < 2 * 4 * DSTRIDE; i += 128) {
        int b = i / (4 * DSTRIDE);
        int rem = i - b * (4 * DSTRIDE);
        doc[b * DOCN + 64 * DSTRIDE + rem] = 0;
    }
    __syncthreads();

    conv_mma_phase<3>(g_wmma + WOFF3, b3, doc, pp, feats, 0, tid);
    conv_mma_phase<4>(g_wmma + WOFF4, b4, doc, pp, feats, 1, tid);
    conv_mma_phase<5>(g_wmma + WOFF5, b5, doc, pp, feats, 2, tid);

    // FC epilogue: out[n, i] = fc_b[i] + feats . fcT[:, i]
    const int i = tid;
    #pragma unroll
    for (int b = 0; b < 2; ++b) {
        float acc = fc_b[i];
        #pragma unroll 8
        for (int k = 0; k < 3 * C_; ++k) acc += feats[b * 384 + k] * fcT[k * E_ + i];
        out[(n0 + b) * E_ + i] = acc;
    }
}

// ---------------- launch ----------------
extern "C" void kernel_launch(void* const* d_in, const int* in_sizes, int n_in,
                              void* d_out, int out_size) {
    const int*   word2news     = (const int*)d_in[0];
    const int*   word2news_len = (const int*)d_in[1];
    const int*   news_words    = (const int*)d_in[2];
    const float* table         = (const float*)d_in[3];
    const float* in_w          = (const float*)d_in[4];
    const float* in_b          = (const float*)d_in[5];
    const float* out_w         = (const float*)d_in[6];
    const float* out_b         = (const float*)d_in[7];
    const float* w3            = (const float*)d_in[8];
    const float* b3            = (const float*)d_in[9];
    const float* w4            = (const float*)d_in[10];
    const float* b4            = (const float*)d_in[11];
    const float* w5            = (const float*)d_in[12];
    const float* b5            = (const float*)d_in[13];
    const float* fc_w          = (const float*)d_in[14];
    const float* fc_b          = (const float*)d_in[15];
    float* out = (float*)d_out;

    float *wqT, *wvT, *woT, *fcT;
    cudaGetSymbolAddress((void**)&wqT, g_wqT);
    cudaGetSymbolAddress((void**)&wvT, g_wvT);
    cudaGetSymbolAddress((void**)&woT, g_woT);
    cudaGetSymbolAddress((void**)&fcT, g_fcT);

    const int word_smem = (int)sizeof(WSmem);
    const int conv_smem = (2 * DOCN + 512 + 768 + 128) * 4;   // ~77 KB
    cudaFuncSetAttribute(word_embed_kernel,
                         cudaFuncAttributeMaxDynamicSharedMemorySize, word_smem);
    cudaFuncSetAttribute(conv_mma_kernel,
                         cudaFuncAttributeMaxDynamicSharedMemorySize, conv_smem);

    prep_t_kernel<<<(3 * PSEG0 + 255) / 256, 256>>>(in_w, out_w);
    prep_fc_kernel<<<(PSEG3 + 255) / 256, 256>>>(fc_w);
    prep_w_kernel<<<(PREPW_TOTAL + 255) / 256, 256>>>(w3, w4, w5);

    word_embed_kernel<<<V_ / WPB, 128, word_smem>>>(
        word2news, word2news_len, table, in_w, in_b, out_b, wqT, wvT, woT);

    conv_mma_kernel<<<N_ / 2, 128, conv_smem>>>(news_words, b3, b4, b5, fcT, fc_b, out);
}

// round 10
// speedup vs baseline: 1.4193x; 1.0476x over previous
#include <cuda_runtime.h>
#include <cuda_bf16.h>
#include <cstdint>

// Problem constants
#define V_  20000
#define M_  32
#define E_  128
#define H_  4
#define N_  8192
#define L_  64
#define C_  128
#define WPB 2          // words per block in word_embed kernel

// conv doc tile geometry (unswizzled, bank-conflict-free stride)
#define DSTRIDE 132            // floats per row (132 mod 32 = 4 -> conflict-free)
#define DOCROWS 68             // 64 + 4 pad rows (pads only feed discarded t)
#define DOCN   (DOCROWS * DSTRIDE)

// ---------------- device scratch (no allocations allowed) ----------------
__device__ float g_word_embeds[V_ * E_];          // [V,E]
__device__ float g_wqT[E_ * E_];                  // [e][i] = Wq[i][e]
__device__ float g_wvT[E_ * E_];                  // [e][i] = Wv[i][e]
__device__ float g_woT[E_ * E_];                  // [e][i] = out_w[i][e]
__device__ float g_fcT[3 * C_ * E_];              // [i][c] = fc_w[c][i]
// fragment-packed tf32 conv weights (+256 pad uint4 for unguarded prefetch)
__device__ uint4 g_wmma[49152 + 256];
#define WOFF3 0
#define WOFF4 12288
#define WOFF5 28672

// ---------------- tf32 helpers ----------------
__device__ __forceinline__ uint32_t f2tf32(float x) {
    uint32_t u;
    asm("cvt.rna.tf32.f32 %0, %1;" : "=r"(u) : "f"(x));
    return u;
}

__device__ __forceinline__ void mma_tf32(float* d,
                                         uint32_t a0, uint32_t a1, uint32_t a2, uint32_t a3,
                                         uint32_t b0, uint32_t b1) {
    asm volatile(
        "mma.sync.aligned.m16n8k8.row.col.f32.tf32.tf32.f32 "
        "{%0,%1,%2,%3}, {%4,%5,%6,%7}, {%8,%9}, {%0,%1,%2,%3};"
        : "+f"(d[0]), "+f"(d[1]), "+f"(d[2]), "+f"(d[3])
        : "r"(a0), "r"(a1), "r"(a2), "r"(a3), "r"(b0), "r"(b1));
}

// ---------------- prep kernels (three launches: word lands at ncu index 3) --
#define PSEG0 (E_ * E_)
#define PSEG3 (3 * C_ * E_)
#define PW3   (3 * 16 * 1024)
#define PW4   (4 * 16 * 1024)
#define PW5   (5 * 16 * 1024)
#define PREPW_TOTAL (PW3 + PW4 + PW5)

__global__ void prep_t_kernel(const float* __restrict__ in_w,
                              const float* __restrict__ out_w) {
    int idx = blockIdx.x * blockDim.x + threadIdx.x;
    if (idx >= 3 * PSEG0) return;
    int seg = idx / PSEG0;
    int r = idx - seg * PSEG0;
    int e = r >> 7, i = r & 127;
    if (seg == 0)      g_wqT[r] = in_w[i * E_ + e];
    else if (seg == 1) g_wvT[r] = in_w[2 * E_ * E_ + i * E_ + e];
    else               g_woT[r] = out_w[i * E_ + e];
}

__global__ void prep_fc_kernel(const float* __restrict__ fc_w) {
    int idx = blockIdx.x * blockDim.x + threadIdx.x;
    if (idx >= PSEG3) return;
    int i = idx >> 7, c = idx & 127;
    g_fcT[idx] = fc_w[c * (3 * C_) + i];
}

__device__ __forceinline__ void prep_wmma_one(const float* __restrict__ w, int K,
                                              int dst_off_u4, int idx) {
    int s    = idx >> 10;
    int rem  = idx & 1023;
    int p    = rem >> 7;
    int lane = (rem >> 2) & 31;
    int q    = rem & 3;
    int j  = s >> 4, ec = s & 15;
    int nt = 2 * p + (q >> 1);
    int kk = (lane & 3) + 4 * (q & 1);
    int c  = nt * 8 + (lane >> 2);
    int e  = ec * 8 + kk;
    float v = w[(c * E_ + e) * K + j];
    reinterpret_cast<uint32_t*>(g_wmma)[dst_off_u4 * 4 + idx] = f2tf32(v);
}

__global__ void prep_w_kernel(const float* __restrict__ w3,
                              const float* __restrict__ w4,
                              const float* __restrict__ w5) {
    int idx = blockIdx.x * blockDim.x + threadIdx.x;
    if (idx >= PREPW_TOTAL) return;
    if (idx < PW3) { prep_wmma_one(w3, 3, WOFF3, idx); return; }
    idx -= PW3;
    if (idx < PW4) { prep_wmma_one(w4, 4, WOFF4, idx); return; }
    idx -= PW4;
    prep_wmma_one(w5, 5, WOFF5, idx);
}

// ---------------- word embedding kernel: 2 words per block ----------------
struct WSmem {
    float ctx[WPB][M_][E_ + 1];
    float q[WPB][E_];
    float qh[WPB][E_];
    float g[WPB][H_][E_];
    float ch[WPB][H_][E_];
    float o[WPB][E_];
    float attn[WPB][H_][M_];
    float cb[WPB][H_];
    int   idx[WPB][M_];
    int   len[WPB];
};

__global__ __launch_bounds__(128) void word_embed_kernel(
    const int* __restrict__ word2news, const int* __restrict__ word2news_len,
    const float* __restrict__ table,
    const float* __restrict__ in_w, const float* __restrict__ in_b,
    const float* __restrict__ out_b,
    const float* __restrict__ wqT, const float* __restrict__ wvT,
    const float* __restrict__ woT)
{
    extern __shared__ char smem_raw[];
    WSmem& s = *reinterpret_cast<WSmem*>(smem_raw);

    const int v0 = blockIdx.x * WPB;
    const int tid = threadIdx.x;
    const int lane = tid & 31, warp = tid >> 5;

    if (tid < WPB * M_) {
        int w = tid >> 5, m = tid & 31;
        s.idx[w][m] = word2news[(v0 + w) * M_ + m];
    }
    if (tid < WPB) s.len[tid] = word2news_len[v0 + tid];
    __syncthreads();

    // gather ctx rows via float4: warp handles row m = m4*4 + warp (m4 = 0..7)
    #pragma unroll
    for (int w = 0; w < WPB; ++w)
        #pragma unroll
        for (int m4 = 0; m4 < 8; ++m4) {
            int m = m4 * 4 + warp;
            float4 v = *reinterpret_cast<const float4*>(
                &table[s.idx[w][m] * E_ + lane * 4]);
            s.ctx[w][m][lane * 4 + 0] = v.x;
            s.ctx[w][m][lane * 4 + 1] = v.y;
            s.ctx[w][m][lane * 4 + 2] = v.z;
            s.ctx[w][m][lane * 4 + 3] = v.w;
        }
    __syncthreads();

    // masked mean query: branchless, fully unrolled
    #pragma unroll
    for (int w = 0; w < WPB; ++w) {
        int len = s.len[w];
        float inv = 1.0f / (float)(len > 0 ? len : 1);
        float a = 0.0f;
        #pragma unroll
        for (int m = 0; m < M_; ++m) {
            float val = s.ctx[w][m][tid];
            a += (m < len) ? val : 0.0f;
        }
        s.q[w][tid] = a * inv;
    }
    __syncthreads();

    // qh = q @ Wq^T + bq
    {
        float acc[WPB];
        #pragma unroll
        for (int w = 0; w < WPB; ++w) acc[w] = 0.0f;
        #pragma unroll 8
        for (int e = 0; e < E_; ++e) {
            float wq = wqT[e * E_ + tid];
            #pragma unroll
            for (int w = 0; w < WPB; ++w) acc[w] += s.q[w][e] * wq;
        }
        float bq = in_b[tid];
        #pragma unroll
        for (int w = 0; w < WPB; ++w) s.qh[w][tid] = acc[w] + bq;
    }
    __syncthreads();

    // g_h[e] = sum_d qh[h*32+d] * Wk[h*32+d][e]
    #pragma unroll
    for (int h = 0; h < H_; ++h) {
        float acc[WPB];
        #pragma unroll
        for (int w = 0; w < WPB; ++w) acc[w] = 0.0f;
        #pragma unroll 8
        for (int d = 0; d < 32; ++d) {
            float wk = in_w[(E_ + h * 32 + d) * E_ + tid];
            #pragma unroll
            for (int w = 0; w < WPB; ++w) acc[w] += s.qh[w][h * 32 + d] * wk;
        }
        #pragma unroll
        for (int w = 0; w < WPB; ++w) s.g[w][h][tid] = acc[w];
    }
    if (tid < WPB * H_) {
        int w = tid >> 2, h = tid & 3;
        float c = 0.0f;
        #pragma unroll 8
        for (int d = 0; d < 32; ++d) c += s.qh[w][h * 32 + d] * in_b[E_ + h * 32 + d];
        s.cb[w][h] = c;
    }
    __syncthreads();

    // scores + per-head warp softmax: thread = (h = warp, m = lane)
    {
        const int h = warp, m = lane;
        #pragma unroll
        for (int w = 0; w < WPB; ++w) {
            float sc = s.cb[w][h];
            #pragma unroll 8
            for (int e = 0; e < E_; ++e) sc += s.ctx[w][m][e] * s.g[w][h][e];
            sc *= 0.17677669529663688f;               // 1/sqrt(32)
            if (m >= s.len[w]) sc = -1e30f;
            float wm = sc;
            #pragma unroll
            for (int o = 16; o; o >>= 1) wm = fmaxf(wm, __shfl_xor_sync(0xFFFFFFFFu, wm, o));
            float p = __expf(sc - wm);
            float ps = p;
            #pragma unroll
            for (int o = 16; o; o >>= 1) ps += __shfl_xor_sync(0xFFFFFFFFu, ps, o);
            s.attn[w][h][m] = p / ps;
        }
    }
    __syncthreads();

    // ch_h[e] = sum_m attn[h,m]*ctx[m][e]
    #pragma unroll
    for (int w = 0; w < WPB; ++w)
        #pragma unroll
        for (int h = 0; h < H_; ++h) {
            float c = 0.0f;
            #pragma unroll 8
            for (int m = 0; m < M_; ++m) c += s.attn[w][h][m] * s.ctx[w][m][tid];
            s.ch[w][h][tid] = c;
        }
    __syncthreads();

    // o[i] = ch_{h(i)} . Wv[i] + bv[i]
    {
        const int h = warp;
        float acc[WPB];
        #pragma unroll
        for (int w = 0; w < WPB; ++w) acc[w] = 0.0f;
        #pragma unroll 8
        for (int e = 0; e < E_; ++e) {
            float wv = wvT[e * E_ + tid];
            #pragma unroll
            for (int w = 0; w < WPB; ++w) acc[w] += s.ch[w][h][e] * wv;
        }
        float bv = in_b[2 * E_ + tid];
        #pragma unroll
        for (int w = 0; w < WPB; ++w) s.o[w][tid] = acc[w] + bv;
    }
    __syncthreads();

    // out proj
    {
        float acc[WPB];
        #pragma unroll
        for (int w = 0; w < WPB; ++w) acc[w] = 0.0f;
        #pragma unroll 8
        for (int e = 0; e < E_; ++e) {
            float wo = woT[e * E_ + tid];
            #pragma unroll
            for (int w = 0; w < WPB; ++w) acc[w] += s.o[w][e] * wo;
        }
        float ob = out_b[tid];
        #pragma unroll
        for (int w = 0; w < WPB; ++w)
            g_word_embeds[(v0 + w) * E_ + tid] = (s.len[w] > 0) ? (acc[w] + ob) : 0.0f;
    }
}

// ---------------- conv (tf32 mma) + maxpool + FC: 2 news per block ----------
// 256 threads = 8 warps; warp = (news = w>>2, t-quarter = w&3) -> 16 warps/SM.
// Each warp: 1 mtile (16 t-rows) x 16 ntiles, B register ping-pong pipeline.
#define CONV_STEP(sv, buf)                                                        \
    do {                                                                          \
        const int j_ = (sv) >> 4, ec_ = (sv) & 15;                                \
        const uint32_t* dp = dbase + (tb + j_ + (lane >> 2)) * DSTRIDE            \
                             + ec_ * 8 + (lane & 3);                              \
        uint32_t a0 = dp[0],           a1 = dp[8 * DSTRIDE];                      \
        uint32_t a2 = dp[4],           a3 = dp[8 * DSTRIDE + 4];                  \
        _Pragma("unroll")                                                         \
        for (int p = 0; p < 8; ++p) {                                             \
            uint4 bb = (buf)[p];                                                  \
            mma_tf32(d[2 * p],     a0, a1, a2, a3, bb.x, bb.y);                   \
            mma_tf32(d[2 * p + 1], a0, a1, a2, a3, bb.z, bb.w);                   \
        }                                                                         \
    } while (0)

template <int K>
__device__ __forceinline__ void conv_mma_phase(
    const uint4* __restrict__ B, const float* __restrict__ bias,
    const uint32_t* __restrict__ doc, float* pp, float* feats, int kidx, int tid)
{
    const int lane = tid & 31, warp = tid >> 5;
    const int news = warp >> 2;
    const int tb = (warp & 3) * 16;
    const uint32_t* dbase = doc + news * DOCN;
    constexpr int S = K * 16;                  // even

    float d[16][4];
    #pragma unroll
    for (int nt = 0; nt < 16; ++nt)
        #pragma unroll
        for (int k = 0; k < 4; ++k) d[nt][k] = 0.0f;

    const uint4* bp = B + lane;
    uint4 bufA[8], bufB[8];
    #pragma unroll
    for (int p = 0; p < 8; ++p) bufA[p] = bp[p * 32];          // step 0

    for (int s = 0; s < S; s += 2) {
        #pragma unroll
        for (int p = 0; p < 8; ++p) bufB[p] = bp[(s + 1) * 256 + p * 32];
        CONV_STEP(s, bufA);
        #pragma unroll
        for (int p = 0; p < 8; ++p) bufA[p] = bp[(s + 2) * 256 + p * 32];  // padded
        CONV_STEP(s + 1, bufB);
    }

    // max over valid t within warp's mtile, then across lane-groups
    constexpr int T = L_ - K + 1;
    #pragma unroll
    for (int nt = 0; nt < 16; ++nt)
        #pragma unroll
        for (int r = 0; r < 2; ++r) {
            float m = -1e30f;
            #pragma unroll
            for (int rr = 0; rr < 2; ++rr) {
                int tl = tb + (lane >> 2) + 8 * rr;
                if (tl < T) m = fmaxf(m, d[nt][2 * rr + r]);
            }
            m = fmaxf(m, __shfl_xor_sync(0xFFFFFFFFu, m, 4));
            m = fmaxf(m, __shfl_xor_sync(0xFFFFFFFFu, m, 8));
            m = fmaxf(m, __shfl_xor_sync(0xFFFFFFFFu, m, 16));
            if (lane < 4) pp[warp * 128 + nt * 8 + 2 * lane + r] = m;
        }
    __syncthreads();
    {
        const int c = tid & 127, b = tid >> 7;
        float v = pp[(b * 4) * 128 + c];
        v = fmaxf(v, pp[(b * 4 + 1) * 128 + c]);
        v = fmaxf(v, pp[(b * 4 + 2) * 128 + c]);
        v = fmaxf(v, pp[(b * 4 + 3) * 128 + c]);
        feats[b * 384 + kidx * 128 + c] = fmaxf(v + bias[c], 0.0f);
    }
    __syncthreads();
}

__global__ __launch_bounds__(256) void conv_mma_kernel(
    const int* __restrict__ news_words,
    const float* __restrict__ b3, const float* __restrict__ b4, const float* __restrict__ b5,
    const float* __restrict__ fcT, const float* __restrict__ fc_b,
    float* __restrict__ out)
{
    extern __shared__ uint32_t cs[];
    uint32_t* doc   = cs;                               // 2*DOCN u32 (tf32 bits)
    float*    pp    = (float*)(cs + 2 * DOCN);          // 8*128
    float*    feats = pp + 1024;                        // 2*384
    int*      idx2  = (int*)(feats + 768);              // 128

    const int n0 = blockIdx.x * 2;
    const int tid = threadIdx.x;

    if (tid < 128) idx2[tid] = news_words[n0 * L_ + tid];   // 2*64 indices
    __syncthreads();

    // gather doc rows: group g = tid>>7 handles news g, col = tid&127
    {
        const int g = tid >> 7, col = tid & 127;
        #pragma unroll 4
        for (int l = 0; l < L_; ++l) {
            float v = g_word_embeds[idx2[g * L_ + l] * E_ + col];
            doc[g * DOCN + l * DSTRIDE + col] = f2tf32(v);
        }
    }
    // zero pad rows 64..67 of each news
    for (int i = tid; i < 2 * 4 * DSTRIDE; i += 256) {
        int b = i / (4 * DSTRIDE);
        int rem = i - b * (4 * DSTRIDE);
        doc[b * DOCN + 64 * DSTRIDE + rem] = 0;
    }
    __syncthreads();

    conv_mma_phase<3>(g_wmma + WOFF3, b3, doc, pp, feats, 0, tid);
    conv_mma_phase<4>(g_wmma + WOFF4, b4, doc, pp, feats, 1, tid);
    conv_mma_phase<5>(g_wmma + WOFF5, b5, doc, pp, feats, 2, tid);

    // FC epilogue: out[n, i] = fc_b[i] + feats . fcT[:, i]
    {
        const int i = tid & 127, b = tid >> 7;
        float acc = fc_b[i];
        #pragma unroll 8
        for (int k = 0; k < 3 * C_; ++k) acc += feats[b * 384 + k] * fcT[k * E_ + i];
        out[(n0 + b) * E_ + i] = acc;
    }
}

// ---------------- launch ----------------
extern "C" void kernel_launch(void* const* d_in, const int* in_sizes, int n_in,
                              void* d_out, int out_size) {
    const int*   word2news     = (const int*)d_in[0];
    const int*   word2news_len = (const int*)d_in[1];
    const int*   news_words    = (const int*)d_in[2];
    const float* table         = (const float*)d_in[3];
    const float* in_w          = (const float*)d_in[4];
    const float* in_b          = (const float*)d_in[5];
    const float* out_w         = (const float*)d_in[6];
    const float* out_b         = (const float*)d_in[7];
    const float* w3            = (const float*)d_in[8];
    const float* b3            = (const float*)d_in[9];
    const float* w4            = (const float*)d_in[10];
    const float* b4            = (const float*)d_in[11];
    const float* w5            = (const float*)d_in[12];
    const float* b5            = (const float*)d_in[13];
    const float* fc_w          = (const float*)d_in[14];
    const float* fc_b          = (const float*)d_in[15];
    float* out = (float*)d_out;

    float *wqT, *wvT, *woT, *fcT;
    cudaGetSymbolAddress((void**)&wqT, g_wqT);
    cudaGetSymbolAddress((void**)&wvT, g_wvT);
    cudaGetSymbolAddress((void**)&woT, g_woT);
    cudaGetSymbolAddress((void**)&fcT, g_fcT);

    const int word_smem = (int)sizeof(WSmem);
    const int conv_smem = (2 * DOCN + 1024 + 768 + 128) * 4;   // ~79.5 KB
    cudaFuncSetAttribute(word_embed_kernel,
                         cudaFuncAttributeMaxDynamicSharedMemorySize, word_smem);
    cudaFuncSetAttribute(conv_mma_kernel,
                         cudaFuncAttributeMaxDynamicSharedMemorySize, conv_smem);

    prep_t_kernel<<<(3 * PSEG0 + 255) / 256, 256>>>(in_w, out_w);
    prep_fc_kernel<<<(PSEG3 + 255) / 256, 256>>>(fc_w);
    prep_w_kernel<<<(PREPW_TOTAL + 255) / 256, 256>>>(w3, w4, w5);

    word_embed_kernel<<<V_ / WPB, 128, word_smem>>>(
        word2news, word2news_len, table, in_w, in_b, out_b, wqT, wvT, woT);

    conv_mma_kernel<<<N_ / 2, 256, conv_smem>>>(news_words, b3, b4, b5, fcT, fc_b, out);
}

// round 11
// speedup vs baseline: 1.7012x; 1.1986x over previous
#include <cuda_runtime.h>
#include <cuda_bf16.h>
#include <cstdint>

// Problem constants
#define V_  20000
#define M_  32
#define E_  128
#define H_  4
#define N_  8192
#define L_  64
#define C_  128
#define WPB 2          // words per block in word_embed kernel

// conv doc tile geometry (unswizzled, bank-conflict-free stride)
#define DSTRIDE 132            // floats per row (132 mod 32 = 4 -> conflict-free)
#define DOCROWS 68             // 64 + 4 pad rows (pads only feed discarded t)
#define DOCN   (DOCROWS * DSTRIDE)

// ---------------- device scratch (no allocations allowed) ----------------
__device__ float g_word_embeds[V_ * E_];          // [V,E]
__device__ float g_wqT[E_ * E_];                  // [e][i] = Wq[i][e]
__device__ float g_wvT[E_ * E_];                  // [e][i] = Wv[i][e]
__device__ float g_woT[E_ * E_];                  // [e][i] = out_w[i][e]
__device__ float g_fcT[3 * C_ * E_];              // [i][c] = fc_w[c][i]
// fragment-packed tf32 conv weights (+256 pad uint4 for unguarded prefetch)
__device__ uint4 g_wmma[49152 + 256];
#define WOFF3 0
#define WOFF4 12288
#define WOFF5 28672

// ---------------- tf32 helpers ----------------
__device__ __forceinline__ uint32_t f2tf32(float x) {
    uint32_t u;
    asm("cvt.rna.tf32.f32 %0, %1;" : "=r"(u) : "f"(x));
    return u;
}

__device__ __forceinline__ void mma_tf32(float* d,
                                         uint32_t a0, uint32_t a1, uint32_t a2, uint32_t a3,
                                         uint32_t b0, uint32_t b1) {
    asm volatile(
        "mma.sync.aligned.m16n8k8.row.col.f32.tf32.tf32.f32 "
        "{%0,%1,%2,%3}, {%4,%5,%6,%7}, {%8,%9}, {%0,%1,%2,%3};"
        : "+f"(d[0]), "+f"(d[1]), "+f"(d[2]), "+f"(d[3])
        : "r"(a0), "r"(a1), "r"(a2), "r"(a3), "r"(b0), "r"(b1));
}

// ---------------- prep kernels (three launches: word lands at ncu index 3) --
#define PSEG0 (E_ * E_)
#define PSEG3 (3 * C_ * E_)
#define PW3   (3 * 16 * 1024)
#define PW4   (4 * 16 * 1024)
#define PW5   (5 * 16 * 1024)
#define PREPW_TOTAL (PW3 + PW4 + PW5)

__global__ void prep_t_kernel(const float* __restrict__ in_w,
                              const float* __restrict__ out_w) {
    int idx = blockIdx.x * blockDim.x + threadIdx.x;
    if (idx >= 3 * PSEG0) return;
    int seg = idx / PSEG0;
    int r = idx - seg * PSEG0;
    int e = r >> 7, i = r & 127;
    if (seg == 0)      g_wqT[r] = in_w[i * E_ + e];
    else if (seg == 1) g_wvT[r] = in_w[2 * E_ * E_ + i * E_ + e];
    else               g_woT[r] = out_w[i * E_ + e];
}

__global__ void prep_fc_kernel(const float* __restrict__ fc_w) {
    int idx = blockIdx.x * blockDim.x + threadIdx.x;
    if (idx >= PSEG3) return;
    int i = idx >> 7, c = idx & 127;
    g_fcT[idx] = fc_w[c * (3 * C_) + i];
}

__device__ __forceinline__ void prep_wmma_one(const float* __restrict__ w, int K,
                                              int dst_off_u4, int idx) {
    int s    = idx >> 10;
    int rem  = idx & 1023;
    int p    = rem >> 7;
    int lane = (rem >> 2) & 31;
    int q    = rem & 3;
    int j  = s >> 4, ec = s & 15;
    int nt = 2 * p + (q >> 1);
    int kk = (lane & 3) + 4 * (q & 1);
    int c  = nt * 8 + (lane >> 2);
    int e  = ec * 8 + kk;
    float v = w[(c * E_ + e) * K + j];
    reinterpret_cast<uint32_t*>(g_wmma)[dst_off_u4 * 4 + idx] = f2tf32(v);
}

__global__ void prep_w_kernel(const float* __restrict__ w3,
                              const float* __restrict__ w4,
                              const float* __restrict__ w5) {
    int idx = blockIdx.x * blockDim.x + threadIdx.x;
    if (idx >= PREPW_TOTAL) return;
    if (idx < PW3) { prep_wmma_one(w3, 3, WOFF3, idx); return; }
    idx -= PW3;
    if (idx < PW4) { prep_wmma_one(w4, 4, WOFF4, idx); return; }
    idx -= PW4;
    prep_wmma_one(w5, 5, WOFF5, idx);
}

// ---------------- word embedding kernel: 2 words per block ----------------
struct WSmem {
    float ctx[WPB][M_][E_ + 1];
    float q[WPB][E_];
    float qh[WPB][E_];
    float g[WPB][H_][E_];
    float ch[WPB][H_][E_];
    float o[WPB][E_];
    float attn[WPB][H_][M_];
    float cb[WPB][H_];
    int   idx[WPB][M_];
    int   len[WPB];
};

__global__ __launch_bounds__(128) void word_embed_kernel(
    const int* __restrict__ word2news, const int* __restrict__ word2news_len,
    const float* __restrict__ table,
    const float* __restrict__ in_w, const float* __restrict__ in_b,
    const float* __restrict__ out_b,
    const float* __restrict__ wqT, const float* __restrict__ wvT,
    const float* __restrict__ woT)
{
    extern __shared__ char smem_raw[];
    WSmem& s = *reinterpret_cast<WSmem*>(smem_raw);

    const int v0 = blockIdx.x * WPB;
    const int tid = threadIdx.x;
    const int lane = tid & 31, warp = tid >> 5;

    if (tid < WPB * M_) {
        int w = tid >> 5, m = tid & 31;
        s.idx[w][m] = word2news[(v0 + w) * M_ + m];
    }
    if (tid < WPB) s.len[tid] = word2news_len[v0 + tid];
    __syncthreads();

    // gather ctx rows via float4: warp handles row m = m4*4 + warp (m4 = 0..7)
    #pragma unroll
    for (int w = 0; w < WPB; ++w)
        #pragma unroll
        for (int m4 = 0; m4 < 8; ++m4) {
            int m = m4 * 4 + warp;
            float4 v = *reinterpret_cast<const float4*>(
                &table[s.idx[w][m] * E_ + lane * 4]);
            s.ctx[w][m][lane * 4 + 0] = v.x;
            s.ctx[w][m][lane * 4 + 1] = v.y;
            s.ctx[w][m][lane * 4 + 2] = v.z;
            s.ctx[w][m][lane * 4 + 3] = v.w;
        }
    __syncthreads();

    // masked mean query: branchless, fully unrolled
    #pragma unroll
    for (int w = 0; w < WPB; ++w) {
        int len = s.len[w];
        float inv = 1.0f / (float)(len > 0 ? len : 1);
        float a = 0.0f;
        #pragma unroll
        for (int m = 0; m < M_; ++m) {
            float val = s.ctx[w][m][tid];
            a += (m < len) ? val : 0.0f;
        }
        s.q[w][tid] = a * inv;
    }
    __syncthreads();

    // qh = q @ Wq^T + bq
    {
        float acc[WPB];
        #pragma unroll
        for (int w = 0; w < WPB; ++w) acc[w] = 0.0f;
        #pragma unroll 8
        for (int e = 0; e < E_; ++e) {
            float wq = wqT[e * E_ + tid];
            #pragma unroll
            for (int w = 0; w < WPB; ++w) acc[w] += s.q[w][e] * wq;
        }
        float bq = in_b[tid];
        #pragma unroll
        for (int w = 0; w < WPB; ++w) s.qh[w][tid] = acc[w] + bq;
    }
    __syncthreads();

    // g_h[e] = sum_d qh[h*32+d] * Wk[h*32+d][e]
    #pragma unroll
    for (int h = 0; h < H_; ++h) {
        float acc[WPB];
        #pragma unroll
        for (int w = 0; w < WPB; ++w) acc[w] = 0.0f;
        #pragma unroll 8
        for (int d = 0; d < 32; ++d) {
            float wk = in_w[(E_ + h * 32 + d) * E_ + tid];
            #pragma unroll
            for (int w = 0; w < WPB; ++w) acc[w] += s.qh[w][h * 32 + d] * wk;
        }
        #pragma unroll
        for (int w = 0; w < WPB; ++w) s.g[w][h][tid] = acc[w];
    }
    if (tid < WPB * H_) {
        int w = tid >> 2, h = tid & 3;
        float c = 0.0f;
        #pragma unroll 8
        for (int d = 0; d < 32; ++d) c += s.qh[w][h * 32 + d] * in_b[E_ + h * 32 + d];
        s.cb[w][h] = c;
    }
    __syncthreads();

    // scores + per-head warp softmax: thread = (h = warp, m = lane)
    {
        const int h = warp, m = lane;
        #pragma unroll
        for (int w = 0; w < WPB; ++w) {
            float sc = s.cb[w][h];
            #pragma unroll 8
            for (int e = 0; e < E_; ++e) sc += s.ctx[w][m][e] * s.g[w][h][e];
            sc *= 0.17677669529663688f;               // 1/sqrt(32)
            if (m >= s.len[w]) sc = -1e30f;
            float wm = sc;
            #pragma unroll
            for (int o = 16; o; o >>= 1) wm = fmaxf(wm, __shfl_xor_sync(0xFFFFFFFFu, wm, o));
            float p = __expf(sc - wm);
            float ps = p;
            #pragma unroll
            for (int o = 16; o; o >>= 1) ps += __shfl_xor_sync(0xFFFFFFFFu, ps, o);
            s.attn[w][h][m] = p / ps;
        }
    }
    __syncthreads();

    // ch_h[e] = sum_m attn[h,m]*ctx[m][e]
    #pragma unroll
    for (int w = 0; w < WPB; ++w)
        #pragma unroll
        for (int h = 0; h < H_; ++h) {
            float c = 0.0f;
            #pragma unroll 8
            for (int m = 0; m < M_; ++m) c += s.attn[w][h][m] * s.ctx[w][m][tid];
            s.ch[w][h][tid] = c;
        }
    __syncthreads();

    // o[i] = ch_{h(i)} . Wv[i] + bv[i]
    {
        const int h = warp;
        float acc[WPB];
        #pragma unroll
        for (int w = 0; w < WPB; ++w) acc[w] = 0.0f;
        #pragma unroll 8
        for (int e = 0; e < E_; ++e) {
            float wv = wvT[e * E_ + tid];
            #pragma unroll
            for (int w = 0; w < WPB; ++w) acc[w] += s.ch[w][h][e] * wv;
        }
        float bv = in_b[2 * E_ + tid];
        #pragma unroll
        for (int w = 0; w < WPB; ++w) s.o[w][tid] = acc[w] + bv;
    }
    __syncthreads();

    // out proj
    {
        float acc[WPB];
        #pragma unroll
        for (int w = 0; w < WPB; ++w) acc[w] = 0.0f;
        #pragma unroll 8
        for (int e = 0; e < E_; ++e) {
            float wo = woT[e * E_ + tid];
            #pragma unroll
            for (int w = 0; w < WPB; ++w) acc[w] += s.o[w][e] * wo;
        }
        float ob = out_b[tid];
        #pragma unroll
        for (int w = 0; w < WPB; ++w)
            g_word_embeds[(v0 + w) * E_ + tid] = (s.len[w] > 0) ? (acc[w] + ob) : 0.0f;
    }
}

// ---------------- conv (tf32 mma) + maxpool + FC: 2 news per block ----------
// 256 threads = 8 warps; warp = (news = w>>2, thalf = (w>>1)&1, chalf = w&1).
// Each warp: 2 mtiles (t-half) x 8 ntiles (channel-half) = 16 MMAs per 4 LDG.128
// -> R9 B-load economics (4 MMA/LDG) at 16 warps/SM. B register ping-pong.
#define CONV_STEP(sv, buf)                                                        \
    do {                                                                          \
        const int j_ = (sv) >> 4, ec_ = (sv) & 15;                                \
        const uint32_t* dp = dbase + (tb + j_ + (lane >> 2)) * DSTRIDE            \
                             + ec_ * 8 + (lane & 3);                              \
        uint32_t a0 = dp[0],                a1 = dp[8 * DSTRIDE];                 \
        uint32_t a2 = dp[4],                a3 = dp[8 * DSTRIDE + 4];             \
        uint32_t a4 = dp[16 * DSTRIDE],     a5 = dp[24 * DSTRIDE];                \
        uint32_t a6 = dp[16 * DSTRIDE + 4], a7 = dp[24 * DSTRIDE + 4];            \
        _Pragma("unroll")                                                         \
        for (int p = 0; p < 4; ++p) {                                             \
            uint4 bb = (buf)[p];                                                  \
            mma_tf32(d[0][2 * p],     a0, a1, a2, a3, bb.x, bb.y);                \
            mma_tf32(d[1][2 * p],     a4, a5, a6, a7, bb.x, bb.y);                \
            mma_tf32(d[0][2 * p + 1], a0, a1, a2, a3, bb.z, bb.w);                \
            mma_tf32(d[1][2 * p + 1], a4, a5, a6, a7, bb.z, bb.w);                \
        }                                                                         \
    } while (0)

template <int K>
__device__ __forceinline__ void conv_mma_phase(
    const uint4* __restrict__ B, const float* __restrict__ bias,
    const uint32_t* __restrict__ doc, float* pp, float* feats, int kidx, int tid)
{
    const int lane = tid & 31, warp = tid >> 5;
    const int news = warp >> 2;
    const int tb = ((warp >> 1) & 1) * 32;
    const int chalf = warp & 1;
    const uint32_t* dbase = doc + news * DOCN;
    constexpr int S = K * 16;                  // even

    float d[2][8][4];
    #pragma unroll
    for (int mt = 0; mt < 2; ++mt)
        #pragma unroll
        for (int nt = 0; nt < 8; ++nt)
            #pragma unroll
            for (int k = 0; k < 4; ++k) d[mt][nt][k] = 0.0f;

    const uint4* bp = B + chalf * 128 + lane;
    uint4 bufA[4], bufB[4];
    #pragma unroll
    for (int p = 0; p < 4; ++p) bufA[p] = bp[p * 32];          // step 0

    for (int s = 0; s < S; s += 2) {
        #pragma unroll
        for (int p = 0; p < 4; ++p) bufB[p] = bp[(s + 1) * 256 + p * 32];
        CONV_STEP(s, bufA);
        #pragma unroll
        for (int p = 0; p < 4; ++p) bufA[p] = bp[(s + 2) * 256 + p * 32];  // padded
        CONV_STEP(s + 1, bufB);
    }

    // max over valid t within warp, then across lane-groups
    constexpr int T = L_ - K + 1;
    #pragma unroll
    for (int nt = 0; nt < 8; ++nt)
        #pragma unroll
        for (int r = 0; r < 2; ++r) {
            float m = -1e30f;
            #pragma unroll
            for (int mt = 0; mt < 2; ++mt)
                #pragma unroll
                for (int rr = 0; rr < 2; ++rr) {
                    int tl = tb + 16 * mt + (lane >> 2) + 8 * rr;
                    if (tl < T) m = fmaxf(m, d[mt][nt][2 * rr + r]);
                }
            m = fmaxf(m, __shfl_xor_sync(0xFFFFFFFFu, m, 4));
            m = fmaxf(m, __shfl_xor_sync(0xFFFFFFFFu, m, 8));
            m = fmaxf(m, __shfl_xor_sync(0xFFFFFFFFu, m, 16));
            if (lane < 4) pp[warp * 64 + nt * 8 + 2 * lane + r] = m;
        }
    __syncthreads();
    {
        // combine t-halves: warp ids b*4 + {0,2} + chalf hold the two halves
        const int c = tid & 127, b = tid >> 7;
        const int ch = c >> 6, cl = c & 63;
        float v = fmaxf(pp[(b * 4 + ch) * 64 + cl],
                        pp[(b * 4 + 2 + ch) * 64 + cl]);
        feats[b * 384 + kidx * 128 + c] = fmaxf(v + bias[c], 0.0f);
    }
    __syncthreads();
}

__global__ __launch_bounds__(256, 2) void conv_mma_kernel(
    const int* __restrict__ news_words,
    const float* __restrict__ b3, const float* __restrict__ b4, const float* __restrict__ b5,
    const float* __restrict__ fcT, const float* __restrict__ fc_b,
    float* __restrict__ out)
{
    extern __shared__ uint32_t cs[];
    uint32_t* doc   = cs;                               // 2*DOCN u32 (tf32 bits)
    float*    pp    = (float*)(cs + 2 * DOCN);          // 8*64
    float*    feats = pp + 512;                         // 2*384
    int*      idx2  = (int*)(feats + 768);              // 128

    const int n0 = blockIdx.x * 2;
    const int tid = threadIdx.x;

    if (tid < 128) idx2[tid] = news_words[n0 * L_ + tid];   // 2*64 indices
    __syncthreads();

    // gather doc rows: group g = tid>>7 handles news g, col = tid&127
    {
        const int g = tid >> 7, col = tid & 127;
        #pragma unroll 4
        for (int l = 0; l < L_; ++l) {
            float v = g_word_embeds[idx2[g * L_ + l] * E_ + col];
            doc[g * DOCN + l * DSTRIDE + col] = f2tf32(v);
        }
    }
    // zero pad rows 64..67 of each news
    for (int i = tid; i < 2 * 4 * DSTRIDE; i += 256) {
        int b = i / (4 * DSTRIDE);
        int rem = i - b * (4 * DSTRIDE);
        doc[b * DOCN + 64 * DSTRIDE + rem] = 0;
    }
    __syncthreads();

    conv_mma_phase<3>(g_wmma + WOFF3, b3, doc, pp, feats, 0, tid);
    conv_mma_phase<4>(g_wmma + WOFF4, b4, doc, pp, feats, 1, tid);
    conv_mma_phase<5>(g_wmma + WOFF5, b5, doc, pp, feats, 2, tid);

    // FC epilogue: out[n, i] = fc_b[i] + feats . fcT[:, i]
    {
        const int i = tid & 127, b = tid >> 7;
        float acc = fc_b[i];
        #pragma unroll 8
        for (int k = 0; k < 3 * C_; ++k) acc += feats[b * 384 + k] * fcT[k * E_ + i];
        out[(n0 + b) * E_ + i] = acc;
    }
}

// ---------------- launch ----------------
extern "C" void kernel_launch(void* const* d_in, const int* in_sizes, int n_in,
                              void* d_out, int out_size) {
    const int*   word2news     = (const int*)d_in[0];
    const int*   word2news_len = (const int*)d_in[1];
    const int*   news_words    = (const int*)d_in[2];
    const float* table         = (const float*)d_in[3];
    const float* in_w          = (const float*)d_in[4];
    const float* in_b          = (const float*)d_in[5];
    const float* out_w         = (const float*)d_in[6];
    const float* out_b         = (const float*)d_in[7];
    const float* w3            = (const float*)d_in[8];
    const float* b3            = (const float*)d_in[9];
    const float* w4            = (const float*)d_in[10];
    const float* b4            = (const float*)d_in[11];
    const float* w5            = (const float*)d_in[12];
    const float* b5            = (const float*)d_in[13];
    const float* fc_w          = (const float*)d_in[14];
    const float* fc_b          = (const float*)d_in[15];
    float* out = (float*)d_out;

    float *wqT, *wvT, *woT, *fcT;
    cudaGetSymbolAddress((void**)&wqT, g_wqT);
    cudaGetSymbolAddress((void**)&wvT, g_wvT);
    cudaGetSymbolAddress((void**)&woT, g_woT);
    cudaGetSymbolAddress((void**)&fcT, g_fcT);

    const int word_smem = (int)sizeof(WSmem);
    const int conv_smem = (2 * DOCN + 512 + 768 + 128) * 4;   // ~75.6 KB
    cudaFuncSetAttribute(word_embed_kernel,
                         cudaFuncAttributeMaxDynamicSharedMemorySize, word_smem);
    cudaFuncSetAttribute(conv_mma_kernel,
                         cudaFuncAttributeMaxDynamicSharedMemorySize, conv_smem);

    prep_t_kernel<<<(3 * PSEG0 + 255) / 256, 256>>>(in_w, out_w);
    prep_fc_kernel<<<(PSEG3 + 255) / 256, 256>>>(fc_w);
    prep_w_kernel<<<(PREPW_TOTAL + 255) / 256, 256>>>(w3, w4, w5);

    word_embed_kernel<<<V_ / WPB, 128, word_smem>>>(
        word2news, word2news_len, table, in_w, in_b, out_b, wqT, wvT, woT);

    conv_mma_kernel<<<N_ / 2, 256, conv_smem>>>(news_words, b3, b4, b5, fcT, fc_b, out);
}